// round 11
// baseline (speedup 1.0000x reference)
#include <cuda_runtime.h>
#include <cuda_fp16.h>
#include <math.h>

#define B 8
#define S 1024
#define D 512
#define H 8
#define HD 64
#define BS (B*S)
#define SCALE 0.044194173824159216f   // 1/sqrt(512)
#define SC2   0.063762069120577f      // SCALE * log2(e)
#define HP 72   // half-element row pad: ldmatrix row banks 4r%32 conflict-free

// ---------------- scratch (static device globals; no allocation) ----------------
__device__ float  g_pe[S * D];
__device__ float  g_w[BS];
__device__ __half g_hh[BS * D];
__device__ __half g_q[B * H * S * HD];   // [b,h,s,d]
__device__ __half g_k[B * H * S * HD];
__device__ __half g_v[B * H * S * HD];
__device__ __half g_att[BS * D];
__device__ __half g_m2[B * S * S];       // fp16 mask premultiplied by SC2

// ---------------- helpers ----------------
__device__ __forceinline__ void mma_f16(float d[4], const unsigned a[4],
                                        unsigned b0, unsigned b1) {
    asm("mma.sync.aligned.m16n8k16.row.col.f32.f16.f16.f32 "
        "{%0,%1,%2,%3}, {%4,%5,%6,%7}, {%8,%9}, {%0,%1,%2,%3};"
        : "+f"(d[0]), "+f"(d[1]), "+f"(d[2]), "+f"(d[3])
        : "r"(a[0]), "r"(a[1]), "r"(a[2]), "r"(a[3]), "r"(b0), "r"(b1));
}
__device__ __forceinline__ void ldmx4(unsigned r[4], unsigned addr) {
    asm volatile("ldmatrix.sync.aligned.m8n8.x4.shared.b16 {%0,%1,%2,%3}, [%4];"
        : "=r"(r[0]), "=r"(r[1]), "=r"(r[2]), "=r"(r[3]) : "r"(addr));
}
__device__ __forceinline__ void ldmx4t(unsigned r[4], unsigned addr) {
    asm volatile("ldmatrix.sync.aligned.m8n8.x4.trans.shared.b16 {%0,%1,%2,%3}, [%4];"
        : "=r"(r[0]), "=r"(r[1]), "=r"(r[2]), "=r"(r[3]) : "r"(addr));
}
__device__ __forceinline__ unsigned h2exp2u(__half2 x) {
    unsigned d;
    asm("ex2.approx.f16x2 %0, %1;" : "=r"(d) : "r"(*(unsigned*)&x));
    return d;
}
__device__ __forceinline__ void cpa16(unsigned dst, const void* src) {
    asm volatile("cp.async.cg.shared.global [%0], [%1], 16;" :: "r"(dst), "l"(src));
}
#define CP_COMMIT() asm volatile("cp.async.commit_group;")
#define CP_WAIT0()  asm volatile("cp.async.wait_group 0;")

// ---------------- kernel 0: PE table ----------------
__global__ void k_pe() {
    int s = blockIdx.x;
    const float c = -logf(10000.0f) / (float)D;
    #pragma unroll
    for (int t = 0; t < 2; t++) {
        int d = threadIdx.x + t * 256;
        int i2 = d & ~1;
        float ang = (float)s * expf(c * (float)i2);
        g_pe[s * D + d] = (d & 1) ? cosf(ang) : sinf(ang);
    }
}

// ---------------- kernel 1: h = emb[x]+PE, width dot ----------------
__global__ void __launch_bounds__(128) k_embed(const int* __restrict__ x,
                                               const float* __restrict__ emb,
                                               const float* __restrict__ Wc,
                                               const float* __restrict__ bc) {
    int bs = blockIdx.x;
    int s = bs & (S - 1);
    int tok = x[bs];
    int t = threadIdx.x;
    const float4* e4 = (const float4*)(emb + (size_t)tok * D);
    const float4* p4 = (const float4*)(g_pe + (size_t)s * D);
    const float4* w4 = (const float4*)Wc;

    float4 e = e4[t], p = p4[t], w = w4[t];
    float4 hv;
    hv.x = e.x + p.x; hv.y = e.y + p.y; hv.z = e.z + p.z; hv.w = e.w + p.w;
    __half2* hh = (__half2*)(g_hh + (size_t)bs * D + t * 4);
    hh[0] = __floats2half2_rn(hv.x, hv.y);
    hh[1] = __floats2half2_rn(hv.z, hv.w);
    float wsum = hv.x * w.x + hv.y * w.y + hv.z * w.z + hv.w * w.w;

    #pragma unroll
    for (int off = 16; off; off >>= 1)
        wsum += __shfl_xor_sync(0xffffffffu, wsum, off);
    __shared__ float red[4];
    if ((t & 31) == 0) red[t >> 5] = wsum;
    __syncthreads();
    if (t == 0)
        g_w[bs] = red[0] + red[1] + red[2] + red[3] + bc[0];
}

// ---------------- kernel 2: per-batch min-max normalize ----------------
__global__ void k_norm() {
    int b = blockIdx.x;
    int t = threadIdx.x;
    float v = g_w[b * S + t];
    float mn = v, mx = v;
    __shared__ float smin[32], smax[32];
    #pragma unroll
    for (int off = 16; off; off >>= 1) {
        mn = fminf(mn, __shfl_xor_sync(0xffffffffu, mn, off));
        mx = fmaxf(mx, __shfl_xor_sync(0xffffffffu, mx, off));
    }
    if ((t & 31) == 0) { smin[t >> 5] = mn; smax[t >> 5] = mx; }
    __syncthreads();
    if (t < 32) {
        mn = smin[t]; mx = smax[t];
        #pragma unroll
        for (int off = 16; off; off >>= 1) {
            mn = fminf(mn, __shfl_xor_sync(0xffffffffu, mn, off));
            mx = fmaxf(mx, __shfl_xor_sync(0xffffffffu, mx, off));
        }
        if (t == 0) { smin[0] = mn; smax[0] = mx; }
    }
    __syncthreads();
    float lo = smin[0], hi = smax[0];
    g_w[b * S + t] = (v - lo) / (hi - lo);
}

// ---------------- kernel 3: mask (fp32 output + fp16*SC2 copy for attention) ----------------
__global__ void __launch_bounds__(256) k_mask(float* __restrict__ mout) {
    int i = blockIdx.x, b = blockIdx.y;
    float w = g_w[b * S + i];
    size_t rowoff = ((size_t)b * S + i) * S;
    float4* mrow4 = (float4*)(mout + rowoff);
    __half* m2row = g_m2 + rowoff;
    bool lower = (i < S / 2);
    int j0 = threadIdx.x * 4;
    float r[4];
    #pragma unroll
    for (int u = 0; u < 4; u++) {
        int j = j0 + u;
        int idx = (S / 2 - 1 - i + j) & (S - 1);
        float origin = (idx < S / 2) ? (1.0f - (float)idx * (1.0f / (float)(S / 2 - 1)))
                                     : ((float)(idx - S / 2) * (1.0f / (float)(S / 2 - 1)));
        bool cmp = (idx >= j);
        bool move = lower ? cmp : !cmp;
        float val = 0.f;
        if (move) {
            float z = (origin - w) * 100.f;
            val = 1.f / (1.f + __expf(z));
        }
        r[u] = val;
    }
    mrow4[threadIdx.x] = make_float4(r[0], r[1], r[2], r[3]);
    __half2 m01 = __floats2half2_rn(r[0] * SC2, r[1] * SC2);
    __half2 m23 = __floats2half2_rn(r[2] * SC2, r[3] * SC2);
    uint2 pack;
    pack.x = *(unsigned*)&m01;
    pack.y = *(unsigned*)&m23;
    *(uint2*)&m2row[j0] = pack;
}

// ---------------- kernel 4: QKV via fp16 mma ----------------
__global__ void __launch_bounds__(256) k_qkv(const float* __restrict__ Wq,
                                             const float* __restrict__ Wk,
                                             const float* __restrict__ Wv) {
    extern __shared__ __half smh[];
    __half* sA = smh;                 // 128 x 72
    __half* sB = smh + 128 * HP;      // 3 x 64 x 72
    int tid = threadIdx.x;
    int w = tid >> 5, lane = tid & 31;
    int r4 = lane >> 2, c4 = lane & 3;
    int m0 = blockIdx.x * 128;
    int h = blockIdx.y;

    #pragma unroll
    for (int t = 0; t < 8; t++) {
        int idx = tid + t * 256;
        int r = idx >> 4, c = (idx & 15) * 4;
        uint2 q = *(const uint2*)&g_hh[(size_t)(m0 + r) * D + h * 64 + c];
        *(uint2*)&sA[r * HP + c] = q;
    }
    const float* Ws[3] = {Wq, Wk, Wv};
    #pragma unroll
    for (int wi = 0; wi < 3; wi++) {
        #pragma unroll
        for (int t = 0; t < 4; t++) {
            int idx = tid + t * 256;
            int r = idx >> 4, c = (idx & 15) * 4;
            float4 v = *(const float4*)&Ws[wi][(size_t)r * 64 + c];
            *(__half2*)&sB[(wi * 64 + r) * HP + c] = __floats2half2_rn(v.x, v.y);
            *(__half2*)&sB[(wi * 64 + r) * HP + c + 2] = __floats2half2_rn(v.z, v.w);
        }
    }
    __syncthreads();

    const __half* Aw = sA + (w * 16) * HP;
    unsigned af[4][4];
    #pragma unroll
    for (int kk = 0; kk < 4; kk++) {
        af[kk][0] = *(const unsigned*)&Aw[r4 * HP + kk * 16 + 2 * c4];
        af[kk][1] = *(const unsigned*)&Aw[(r4 + 8) * HP + kk * 16 + 2 * c4];
        af[kk][2] = *(const unsigned*)&Aw[r4 * HP + kk * 16 + 2 * c4 + 8];
        af[kk][3] = *(const unsigned*)&Aw[(r4 + 8) * HP + kk * 16 + 2 * c4 + 8];
    }

    int row0 = m0 + w * 16 + r4;
    __half* outs[3] = {g_q, g_k, g_v};
    #pragma unroll
    for (int wi = 0; wi < 3; wi++) {
        float acc[8][4];
        #pragma unroll
        for (int nt = 0; nt < 8; nt++) {
            #pragma unroll
            for (int j = 0; j < 4; j++) acc[nt][j] = 0.f;
            #pragma unroll
            for (int kk = 0; kk < 4; kk++) {
                const __half* bp = &sB[(wi * 64 + nt * 8 + r4) * HP + kk * 16 + 2 * c4];
                unsigned b0 = *(const unsigned*)bp;
                unsigned b1 = *(const unsigned*)(bp + 8);
                mma_f16(acc[nt], af[kk], b0, b1);
            }
        }
        int b0r = row0 >> 10, s0 = row0 & (S - 1);
        int b1r = (row0 + 8) >> 10, s1 = (row0 + 8) & (S - 1);
        size_t q0 = (((size_t)b0r * H + h) * S + s0) * HD;
        size_t q1 = (((size_t)b1r * H + h) * S + s1) * HD;
        __half* op = outs[wi];
        #pragma unroll
        for (int nt = 0; nt < 8; nt++) {
            *(__half2*)&op[q0 + nt * 8 + 2 * c4] = __floats2half2_rn(acc[nt][0], acc[nt][1]);
            *(__half2*)&op[q1 + nt * 8 + 2 * c4] = __floats2half2_rn(acc[nt][2], acc[nt][3]);
        }
    }
}

// ---------------- kernel 5: fp16 mma flash attention ----------------
// No-shift softmax with SIMD fp16 epilogue: p = ex2.f16x2(half2(e) * m2),
// exp outputs ARE the PV A-fragments; l via HADD2 tree then fp32.
__global__ void __launch_bounds__(256, 2) k_attn() {
    extern __shared__ __half smh[];
    int tid = threadIdx.x;
    int w = tid >> 5, lane = tid & 31;
    int r4 = lane >> 2, c4 = lane & 3;
    int qt = blockIdx.x & 7;
    int bh = blockIdx.x >> 3;
    int h = bh & 7, b = bh >> 3;
    size_t base = (size_t)bh * S * HD;
    int qw = qt * 128 + w * 16;

    unsigned s_u = (unsigned)__cvta_generic_to_shared(smh);
    unsigned sK_u[2] = {s_u, s_u + 2u * 64 * HP * 2};
    unsigned sV_u[2] = {s_u + 64u * HP * 2, s_u + 3u * 64 * HP * 2};

    unsigned krow = ((lane & 7) * HP + ((lane >> 3) << 3)) * 2;
    unsigned vrow = ((((lane >> 3) & 1) * 8 + (lane & 7)) * HP + ((lane >> 4) << 3)) * 2;

    int srow0 = tid >> 3, sc0 = (tid & 7) * 8;
    int srow1 = (tid + 256) >> 3, sc1 = ((tid + 256) & 7) * 8;
    const __half* gk0 = g_k + base;
    const __half* gv0 = g_v + base;

    // prologue: stage tile 0
    cpa16(sK_u[0] + (srow0 * HP + sc0) * 2, gk0 + srow0 * 64 + sc0);
    cpa16(sK_u[0] + (srow1 * HP + sc1) * 2, gk0 + srow1 * 64 + sc1);
    cpa16(sV_u[0] + (srow0 * HP + sc0) * 2, gv0 + srow0 * 64 + sc0);
    cpa16(sV_u[0] + (srow1 * HP + sc1) * 2, gv0 + srow1 * 64 + sc1);
    CP_COMMIT();

    // Q fragments from global
    unsigned qa[4][4];
    {
        const __half* qb = g_q + base + (size_t)qw * HD;
        #pragma unroll
        for (int kk = 0; kk < 4; kk++) {
            qa[kk][0] = *(const unsigned*)&qb[r4 * 64 + kk * 16 + 2 * c4];
            qa[kk][1] = *(const unsigned*)&qb[(r4 + 8) * 64 + kk * 16 + 2 * c4];
            qa[kk][2] = *(const unsigned*)&qb[r4 * 64 + kk * 16 + 2 * c4 + 8];
            qa[kk][3] = *(const unsigned*)&qb[(r4 + 8) * 64 + kk * 16 + 2 * c4 + 8];
        }
    }

    float o[8][4];
    #pragma unroll
    for (int nt = 0; nt < 8; nt++)
        #pragma unroll
        for (int j = 0; j < 4; j++) o[nt][j] = 0.f;
    float l0 = 0.f, l1 = 0.f;

    const __half* m2row0 = g_m2 + ((size_t)h * S + qw + r4) * S;
    const __half* m2row1 = m2row0 + (size_t)8 * S;

    for (int kt = 0; kt < S / 64; kt++) {
        int cur = kt & 1;
        CP_WAIT0();
        __syncthreads();
        if (kt < S / 64 - 1) {
            int nxt = cur ^ 1;
            const __half* gk = gk0 + (size_t)(kt + 1) * 64 * 64;
            const __half* gv = gv0 + (size_t)(kt + 1) * 64 * 64;
            cpa16(sK_u[nxt] + (srow0 * HP + sc0) * 2, gk + srow0 * 64 + sc0);
            cpa16(sK_u[nxt] + (srow1 * HP + sc1) * 2, gk + srow1 * 64 + sc1);
            cpa16(sV_u[nxt] + (srow0 * HP + sc0) * 2, gv + srow0 * 64 + sc0);
            cpa16(sV_u[nxt] + (srow1 * HP + sc1) * 2, gv + srow1 * 64 + sc1);
            CP_COMMIT();
        }

        // energy = Q K^T
        float e[8][4];
        #pragma unroll
        for (int nt = 0; nt < 8; nt++) {
            #pragma unroll
            for (int j = 0; j < 4; j++) e[nt][j] = 0.f;
            unsigned kb0 = sK_u[cur] + nt * 8 * HP * 2 + krow;
            unsigned bf[4], bf2[4];
            ldmx4(bf, kb0);
            ldmx4(bf2, kb0 + 64);
            mma_f16(e[nt], qa[0], bf[0], bf[1]);
            mma_f16(e[nt], qa[1], bf[2], bf[3]);
            mma_f16(e[nt], qa[2], bf2[0], bf2[1]);
            mma_f16(e[nt], qa[3], bf2[2], bf2[3]);
        }

        // p = ex2.f16x2( half2(e) * m2 )  — outputs are PV A-fragments directly
        int kb = kt * 64;
        unsigned px[8], py[8];
        #pragma unroll
        for (int nt = 0; nt < 8; nt++) {
            __half2 mh0 = *(const __half2*)&m2row0[kb + nt * 8 + 2 * c4];
            __half2 mh1 = *(const __half2*)&m2row1[kb + nt * 8 + 2 * c4];
            __half2 e0 = __floats2half2_rn(e[nt][0], e[nt][1]);
            __half2 e1 = __floats2half2_rn(e[nt][2], e[nt][3]);
            px[nt] = h2exp2u(__hmul2(e0, mh0));
            py[nt] = h2exp2u(__hmul2(e1, mh1));
        }
        // l: HADD2 tree (max partial ~160, safe in fp16), fold to fp32 per tile
        {
            __half2 s0 = __hadd2(
                __hadd2(__hadd2(*(__half2*)&px[0], *(__half2*)&px[1]),
                        __hadd2(*(__half2*)&px[2], *(__half2*)&px[3])),
                __hadd2(__hadd2(*(__half2*)&px[4], *(__half2*)&px[5]),
                        __hadd2(*(__half2*)&px[6], *(__half2*)&px[7])));
            __half2 s1 = __hadd2(
                __hadd2(__hadd2(*(__half2*)&py[0], *(__half2*)&py[1]),
                        __hadd2(*(__half2*)&py[2], *(__half2*)&py[3])),
                __hadd2(__hadd2(*(__half2*)&py[4], *(__half2*)&py[5]),
                        __hadd2(*(__half2*)&py[6], *(__half2*)&py[7])));
            float2 f0 = __half22float2(s0);
            float2 f1 = __half22float2(s1);
            l0 += f0.x + f0.y;
            l1 += f1.x + f1.y;
        }

        // O += P V : px/py are A fragments; V via ldmatrix.trans
        #pragma unroll
        for (int kk = 0; kk < 4; kk++) {
            unsigned pa[4];
            pa[0] = px[2 * kk];
            pa[1] = py[2 * kk];
            pa[2] = px[2 * kk + 1];
            pa[3] = py[2 * kk + 1];
            #pragma unroll
            for (int ntp = 0; ntp < 4; ntp++) {
                unsigned vf[4];
                ldmx4t(vf, sV_u[cur] + (kk * 16 * HP + ntp * 16) * 2 + vrow);
                mma_f16(o[2 * ntp], pa, vf[0], vf[1]);
                mma_f16(o[2 * ntp + 1], pa, vf[2], vf[3]);
            }
        }
    }

    // single end-of-loop reduction of l across the quad
    l0 += __shfl_xor_sync(0xffffffffu, l0, 1);
    l0 += __shfl_xor_sync(0xffffffffu, l0, 2);
    l1 += __shfl_xor_sync(0xffffffffu, l1, 1);
    l1 += __shfl_xor_sync(0xffffffffu, l1, 2);
    float inv0 = 1.f / l0, inv1 = 1.f / l1;
    size_t ob0 = ((size_t)(b * S + qw + r4)) * D + h * 64;
    size_t ob1 = ((size_t)(b * S + qw + r4 + 8)) * D + h * 64;
    #pragma unroll
    for (int nt = 0; nt < 8; nt++) {
        *(__half2*)&g_att[ob0 + nt * 8 + 2 * c4] = __floats2half2_rn(o[nt][0] * inv0, o[nt][1] * inv0);
        *(__half2*)&g_att[ob1 + nt * 8 + 2 * c4] = __floats2half2_rn(o[nt][2] * inv1, o[nt][3] * inv1);
    }
}

// ---------------- kernel 6: out = att @ Wo^T + bo (double-buffered fp16 mma) ----------------
__global__ void __launch_bounds__(256, 2) k_proj(const float* __restrict__ Wo,
                                                 const float* __restrict__ bo,
                                                 float* __restrict__ out) {
    extern __shared__ __half smh[];
    __half* sA[2] = {smh, smh + 128 * HP};
    __half* sB[2] = {smh + 2 * 128 * HP, smh + 2 * 128 * HP + 64 * HP};
    int tid = threadIdx.x;
    int w = tid >> 5, lane = tid & 31;
    int r4 = lane >> 2, c4 = lane & 3;
    int m0 = blockIdx.x * 128;
    int n0 = blockIdx.y * 64;

    unsigned s_u = (unsigned)__cvta_generic_to_shared(smh);
    unsigned sA_u[2] = {s_u, s_u + 128u * HP * 2};

    float acc[8][4];
    #pragma unroll
    for (int nt = 0; nt < 8; nt++)
        #pragma unroll
        for (int j = 0; j < 4; j++) acc[nt][j] = 0.f;

    auto stageA = [&](int buf, int k0) {
        #pragma unroll
        for (int t = 0; t < 4; t++) {
            int idx = tid + t * 256;
            int r = idx >> 3, c = (idx & 7) * 8;
            cpa16(sA_u[buf] + (r * HP + c) * 2, &g_att[(size_t)(m0 + r) * D + k0 + c]);
        }
    };
    auto stageB = [&](int buf, int k0) {
        #pragma unroll
        for (int t = 0; t < 4; t++) {
            int idx = tid + t * 256;
            int r = idx >> 4, c = (idx & 15) * 4;
            float4 v = *(const float4*)&Wo[(size_t)(n0 + r) * D + k0 + c];
            *(__half2*)&sB[buf][r * HP + c] = __floats2half2_rn(v.x, v.y);
            *(__half2*)&sB[buf][r * HP + c + 2] = __floats2half2_rn(v.z, v.w);
        }
    };

    stageA(0, 0);
    CP_COMMIT();
    stageB(0, 0);

    for (int kt = 0; kt < D / 64; kt++) {
        int cur = kt & 1;
        CP_WAIT0();
        __syncthreads();
        if (kt < D / 64 - 1) {
            stageA(cur ^ 1, (kt + 1) * 64);
            CP_COMMIT();
            stageB(cur ^ 1, (kt + 1) * 64);
        }

        const __half* Aw = sA[cur] + (w * 16) * HP;
        unsigned af[4][4];
        #pragma unroll
        for (int kk = 0; kk < 4; kk++) {
            af[kk][0] = *(const unsigned*)&Aw[r4 * HP + kk * 16 + 2 * c4];
            af[kk][1] = *(const unsigned*)&Aw[(r4 + 8) * HP + kk * 16 + 2 * c4];
            af[kk][2] = *(const unsigned*)&Aw[r4 * HP + kk * 16 + 2 * c4 + 8];
            af[kk][3] = *(const unsigned*)&Aw[(r4 + 8) * HP + kk * 16 + 2 * c4 + 8];
        }
        #pragma unroll
        for (int nt = 0; nt < 8; nt++) {
            #pragma unroll
            for (int kk = 0; kk < 4; kk++) {
                const __half* bp = &sB[cur][(nt * 8 + r4) * HP + kk * 16 + 2 * c4];
                unsigned b0 = *(const unsigned*)bp;
                unsigned b1 = *(const unsigned*)(bp + 8);
                mma_f16(acc[nt], af[kk], b0, b1);
            }
        }
    }

    int row0 = m0 + w * 16 + r4;
    #pragma unroll
    for (int nt = 0; nt < 8; nt++) {
        int n = n0 + nt * 8 + 2 * c4;
        float2 bb = *(const float2*)&bo[n];
        float2 v0, v1;
        v0.x = acc[nt][0] + bb.x; v0.y = acc[nt][1] + bb.y;
        v1.x = acc[nt][2] + bb.x; v1.y = acc[nt][3] + bb.y;
        *(float2*)&out[(size_t)row0 * D + n] = v0;
        *(float2*)&out[(size_t)(row0 + 8) * D + n] = v1;
    }
}

// ---------------- launch ----------------
extern "C" void kernel_launch(void* const* d_in, const int* in_sizes, int n_in,
                              void* d_out, int out_size) {
    const int*   x   = (const int*)d_in[0];
    const float* emb = (const float*)d_in[1];
    const float* Wq  = (const float*)d_in[2];
    const float* Wk  = (const float*)d_in[3];
    const float* Wv  = (const float*)d_in[4];
    const float* Wo  = (const float*)d_in[5];
    const float* bo  = (const float*)d_in[6];
    const float* Wc  = (const float*)d_in[7];
    const float* bc  = (const float*)d_in[8];
    float* out = (float*)d_out;
    float* maskout = out + (size_t)B * S * D;

    k_pe<<<S, 256>>>();
    k_embed<<<BS, 128>>>(x, emb, Wc, bc);
    k_norm<<<B, S>>>();
    dim3 mg(S, B);
    k_mask<<<mg, 256>>>(maskout);

    size_t qkv_smem = (128 * HP + 3 * 64 * HP) * sizeof(__half);
    cudaFuncSetAttribute(k_qkv, cudaFuncAttributeMaxDynamicSharedMemorySize, (int)qkv_smem);
    dim3 qg(BS / 128, H);
    k_qkv<<<qg, 256, qkv_smem>>>(Wq, Wk, Wv);

    size_t attn_smem = 4 * 64 * HP * sizeof(__half);
    cudaFuncSetAttribute(k_attn, cudaFuncAttributeMaxDynamicSharedMemorySize, (int)attn_smem);
    k_attn<<<B * H * (S / 128), 256, attn_smem>>>();

    size_t proj_smem = (2 * 128 * HP + 2 * 64 * HP) * sizeof(__half);
    cudaFuncSetAttribute(k_proj, cudaFuncAttributeMaxDynamicSharedMemorySize, (int)proj_smem);
    dim3 pg(BS / 128, D / 64);
    k_proj<<<pg, 256, proj_smem>>>(Wo, bo, out);
}

// round 13
// speedup vs baseline: 1.0348x; 1.0348x over previous
#include <cuda_runtime.h>
#include <cuda_fp16.h>
#include <math.h>

#define B 8
#define S 1024
#define D 512
#define H 8
#define HD 64
#define BS (B*S)
#define SCALE 0.044194173824159216f   // 1/sqrt(512)
#define SC2   0.063762069120577f      // SCALE * log2(e)
#define HP 72   // half-element row pad: ldmatrix row banks 4r%32 conflict-free

// ---------------- scratch (static device globals; no allocation) ----------------
__device__ float  g_pe[S * D];
__device__ float  g_w[BS];
__device__ __half g_hh[BS * D];
__device__ __half g_q[B * H * S * HD];   // [b,h,s,d]
__device__ __half g_k[B * H * S * HD];
__device__ __half g_v[B * H * S * HD];
__device__ __half g_att[BS * D];

// ---------------- helpers ----------------
__device__ __forceinline__ void mma_f16(float d[4], const unsigned a[4],
                                        unsigned b0, unsigned b1) {
    asm("mma.sync.aligned.m16n8k16.row.col.f32.f16.f16.f32 "
        "{%0,%1,%2,%3}, {%4,%5,%6,%7}, {%8,%9}, {%0,%1,%2,%3};"
        : "+f"(d[0]), "+f"(d[1]), "+f"(d[2]), "+f"(d[3])
        : "r"(a[0]), "r"(a[1]), "r"(a[2]), "r"(a[3]), "r"(b0), "r"(b1));
}
__device__ __forceinline__ void ldmx4(unsigned r[4], unsigned addr) {
    asm volatile("ldmatrix.sync.aligned.m8n8.x4.shared.b16 {%0,%1,%2,%3}, [%4];"
        : "=r"(r[0]), "=r"(r[1]), "=r"(r[2]), "=r"(r[3]) : "r"(addr));
}
__device__ __forceinline__ void ldmx4t(unsigned r[4], unsigned addr) {
    asm volatile("ldmatrix.sync.aligned.m8n8.x4.trans.shared.b16 {%0,%1,%2,%3}, [%4];"
        : "=r"(r[0]), "=r"(r[1]), "=r"(r[2]), "=r"(r[3]) : "r"(addr));
}
__device__ __forceinline__ unsigned h2u(float a, float b) {
    __half2 h = __floats2half2_rn(a, b);
    return *(unsigned*)&h;
}
__device__ __forceinline__ void cpa16(unsigned dst, const void* src) {
    asm volatile("cp.async.cg.shared.global [%0], [%1], 16;" :: "r"(dst), "l"(src));
}
#define CP_COMMIT() asm volatile("cp.async.commit_group;")
#define CP_WAIT0()  asm volatile("cp.async.wait_group 0;")

// ---------------- kernel 0: PE table ----------------
__global__ void k_pe() {
    int s = blockIdx.x;
    const float c = -logf(10000.0f) / (float)D;
    #pragma unroll
    for (int t = 0; t < 2; t++) {
        int d = threadIdx.x + t * 256;
        int i2 = d & ~1;
        float ang = (float)s * expf(c * (float)i2);
        g_pe[s * D + d] = (d & 1) ? cosf(ang) : sinf(ang);
    }
}

// ---------------- kernel 1: h = emb[x]+PE, width dot ----------------
__global__ void __launch_bounds__(128) k_embed(const int* __restrict__ x,
                                               const float* __restrict__ emb,
                                               const float* __restrict__ Wc,
                                               const float* __restrict__ bc) {
    int bs = blockIdx.x;
    int s = bs & (S - 1);
    int tok = x[bs];
    int t = threadIdx.x;
    const float4* e4 = (const float4*)(emb + (size_t)tok * D);
    const float4* p4 = (const float4*)(g_pe + (size_t)s * D);
    const float4* w4 = (const float4*)Wc;

    float4 e = e4[t], p = p4[t], w = w4[t];
    float4 hv;
    hv.x = e.x + p.x; hv.y = e.y + p.y; hv.z = e.z + p.z; hv.w = e.w + p.w;
    __half2* hh = (__half2*)(g_hh + (size_t)bs * D + t * 4);
    hh[0] = __floats2half2_rn(hv.x, hv.y);
    hh[1] = __floats2half2_rn(hv.z, hv.w);
    float wsum = hv.x * w.x + hv.y * w.y + hv.z * w.z + hv.w * w.w;

    #pragma unroll
    for (int off = 16; off; off >>= 1)
        wsum += __shfl_xor_sync(0xffffffffu, wsum, off);
    __shared__ float red[4];
    if ((t & 31) == 0) red[t >> 5] = wsum;
    __syncthreads();
    if (t == 0)
        g_w[bs] = red[0] + red[1] + red[2] + red[3] + bc[0];
}

// ---------------- kernel 2: per-batch min-max normalize ----------------
__global__ void k_norm() {
    int b = blockIdx.x;
    int t = threadIdx.x;
    float v = g_w[b * S + t];
    float mn = v, mx = v;
    __shared__ float smin[32], smax[32];
    #pragma unroll
    for (int off = 16; off; off >>= 1) {
        mn = fminf(mn, __shfl_xor_sync(0xffffffffu, mn, off));
        mx = fmaxf(mx, __shfl_xor_sync(0xffffffffu, mx, off));
    }
    if ((t & 31) == 0) { smin[t >> 5] = mn; smax[t >> 5] = mx; }
    __syncthreads();
    if (t < 32) {
        mn = smin[t]; mx = smax[t];
        #pragma unroll
        for (int off = 16; off; off >>= 1) {
            mn = fminf(mn, __shfl_xor_sync(0xffffffffu, mn, off));
            mx = fmaxf(mx, __shfl_xor_sync(0xffffffffu, mx, off));
        }
        if (t == 0) { smin[0] = mn; smax[0] = mx; }
    }
    __syncthreads();
    float lo = smin[0], hi = smax[0];
    g_w[b * S + t] = (v - lo) / (hi - lo);
}

// ---------------- kernel 3: mask ----------------
__global__ void __launch_bounds__(256) k_mask(float* __restrict__ mout) {
    int i = blockIdx.x, b = blockIdx.y;
    float w = g_w[b * S + i];
    float4* mrow4 = (float4*)(mout + ((size_t)b * S + i) * S);
    bool lower = (i < S / 2);
    int j0 = threadIdx.x * 4;
    float r[4];
    #pragma unroll
    for (int u = 0; u < 4; u++) {
        int j = j0 + u;
        int idx = (S / 2 - 1 - i + j) & (S - 1);
        float origin = (idx < S / 2) ? (1.0f - (float)idx * (1.0f / (float)(S / 2 - 1)))
                                     : ((float)(idx - S / 2) * (1.0f / (float)(S / 2 - 1)));
        bool cmp = (idx >= j);
        bool move = lower ? cmp : !cmp;
        float val = 0.f;
        if (move) {
            float z = (origin - w) * 100.f;
            val = 1.f / (1.f + __expf(z));
        }
        r[u] = val;
    }
    mrow4[threadIdx.x] = make_float4(r[0], r[1], r[2], r[3]);
}

// ---------------- kernel 4: QKV via fp16 mma ----------------
__global__ void __launch_bounds__(256) k_qkv(const float* __restrict__ Wq,
                                             const float* __restrict__ Wk,
                                             const float* __restrict__ Wv) {
    extern __shared__ __half smh[];
    __half* sA = smh;                 // 128 x 72
    __half* sB = smh + 128 * HP;      // 3 x 64 x 72
    int tid = threadIdx.x;
    int w = tid >> 5, lane = tid & 31;
    int r4 = lane >> 2, c4 = lane & 3;
    int m0 = blockIdx.x * 128;
    int h = blockIdx.y;

    #pragma unroll
    for (int t = 0; t < 8; t++) {
        int idx = tid + t * 256;
        int r = idx >> 4, c = (idx & 15) * 4;
        uint2 q = *(const uint2*)&g_hh[(size_t)(m0 + r) * D + h * 64 + c];
        *(uint2*)&sA[r * HP + c] = q;
    }
    const float* Ws[3] = {Wq, Wk, Wv};
    #pragma unroll
    for (int wi = 0; wi < 3; wi++) {
        #pragma unroll
        for (int t = 0; t < 4; t++) {
            int idx = tid + t * 256;
            int r = idx >> 4, c = (idx & 15) * 4;
            float4 v = *(const float4*)&Ws[wi][(size_t)r * 64 + c];
            *(__half2*)&sB[(wi * 64 + r) * HP + c] = __floats2half2_rn(v.x, v.y);
            *(__half2*)&sB[(wi * 64 + r) * HP + c + 2] = __floats2half2_rn(v.z, v.w);
        }
    }
    __syncthreads();

    const __half* Aw = sA + (w * 16) * HP;
    unsigned af[4][4];
    #pragma unroll
    for (int kk = 0; kk < 4; kk++) {
        af[kk][0] = *(const unsigned*)&Aw[r4 * HP + kk * 16 + 2 * c4];
        af[kk][1] = *(const unsigned*)&Aw[(r4 + 8) * HP + kk * 16 + 2 * c4];
        af[kk][2] = *(const unsigned*)&Aw[r4 * HP + kk * 16 + 2 * c4 + 8];
        af[kk][3] = *(const unsigned*)&Aw[(r4 + 8) * HP + kk * 16 + 2 * c4 + 8];
    }

    int row0 = m0 + w * 16 + r4;
    __half* outs[3] = {g_q, g_k, g_v};
    #pragma unroll
    for (int wi = 0; wi < 3; wi++) {
        float acc[8][4];
        #pragma unroll
        for (int nt = 0; nt < 8; nt++) {
            #pragma unroll
            for (int j = 0; j < 4; j++) acc[nt][j] = 0.f;
            #pragma unroll
            for (int kk = 0; kk < 4; kk++) {
                const __half* bp = &sB[(wi * 64 + nt * 8 + r4) * HP + kk * 16 + 2 * c4];
                unsigned b0 = *(const unsigned*)bp;
                unsigned b1 = *(const unsigned*)(bp + 8);
                mma_f16(acc[nt], af[kk], b0, b1);
            }
        }
        int b0r = row0 >> 10, s0 = row0 & (S - 1);
        int b1r = (row0 + 8) >> 10, s1 = (row0 + 8) & (S - 1);
        size_t q0 = (((size_t)b0r * H + h) * S + s0) * HD;
        size_t q1 = (((size_t)b1r * H + h) * S + s1) * HD;
        __half* op = outs[wi];
        #pragma unroll
        for (int nt = 0; nt < 8; nt++) {
            *(__half2*)&op[q0 + nt * 8 + 2 * c4] = __floats2half2_rn(acc[nt][0], acc[nt][1]);
            *(__half2*)&op[q1 + nt * 8 + 2 * c4] = __floats2half2_rn(acc[nt][2], acc[nt][3]);
        }
    }
}

// ---------------- kernel 5: fp16 mma flash attention ----------------
// No-shift softmax; QK / softmax / PV interleaved at key-group granularity:
// group g covers keys 16g..16g+15 (QK nt=2g,2g+1 -> softmax -> PV kk=g),
// so group g+1's QK mma overlaps group g's scalar softmax in the scheduler.
__global__ void __launch_bounds__(256, 2) k_attn(const float* __restrict__ mask) {
    extern __shared__ __half smh[];
    int tid = threadIdx.x;
    int w = tid >> 5, lane = tid & 31;
    int r4 = lane >> 2, c4 = lane & 3;
    int qt = blockIdx.x & 7;
    int bh = blockIdx.x >> 3;
    int h = bh & 7, b = bh >> 3;
    size_t base = (size_t)bh * S * HD;
    int qw = qt * 128 + w * 16;

    unsigned s_u = (unsigned)__cvta_generic_to_shared(smh);
    unsigned sK_u[2] = {s_u, s_u + 2u * 64 * HP * 2};
    unsigned sV_u[2] = {s_u + 64u * HP * 2, s_u + 3u * 64 * HP * 2};

    unsigned krow = ((lane & 7) * HP + ((lane >> 3) << 3)) * 2;
    unsigned vrow = ((((lane >> 3) & 1) * 8 + (lane & 7)) * HP + ((lane >> 4) << 3)) * 2;

    int srow0 = tid >> 3, sc0 = (tid & 7) * 8;
    int srow1 = (tid + 256) >> 3, sc1 = ((tid + 256) & 7) * 8;
    const __half* gk0 = g_k + base;
    const __half* gv0 = g_v + base;

    // prologue: stage tile 0
    cpa16(sK_u[0] + (srow0 * HP + sc0) * 2, gk0 + srow0 * 64 + sc0);
    cpa16(sK_u[0] + (srow1 * HP + sc1) * 2, gk0 + srow1 * 64 + sc1);
    cpa16(sV_u[0] + (srow0 * HP + sc0) * 2, gv0 + srow0 * 64 + sc0);
    cpa16(sV_u[0] + (srow1 * HP + sc1) * 2, gv0 + srow1 * 64 + sc1);
    CP_COMMIT();

    // Q fragments from global
    unsigned qa[4][4];
    {
        const __half* qb = g_q + base + (size_t)qw * HD;
        #pragma unroll
        for (int kk = 0; kk < 4; kk++) {
            qa[kk][0] = *(const unsigned*)&qb[r4 * 64 + kk * 16 + 2 * c4];
            qa[kk][1] = *(const unsigned*)&qb[(r4 + 8) * 64 + kk * 16 + 2 * c4];
            qa[kk][2] = *(const unsigned*)&qb[r4 * 64 + kk * 16 + 2 * c4 + 8];
            qa[kk][3] = *(const unsigned*)&qb[(r4 + 8) * 64 + kk * 16 + 2 * c4 + 8];
        }
    }

    float o[8][4];
    #pragma unroll
    for (int nt = 0; nt < 8; nt++)
        #pragma unroll
        for (int j = 0; j < 4; j++) o[nt][j] = 0.f;
    float l0 = 0.f, l1 = 0.f;

    const float* mrow0 = mask + ((size_t)h * S + qw + r4) * S;
    const float* mrow1 = mrow0 + (size_t)8 * S;

    for (int kt = 0; kt < S / 64; kt++) {
        int cur = kt & 1;
        CP_WAIT0();
        __syncthreads();
        if (kt < S / 64 - 1) {
            int nxt = cur ^ 1;
            const __half* gk = gk0 + (size_t)(kt + 1) * 64 * 64;
            const __half* gv = gv0 + (size_t)(kt + 1) * 64 * 64;
            cpa16(sK_u[nxt] + (srow0 * HP + sc0) * 2, gk + srow0 * 64 + sc0);
            cpa16(sK_u[nxt] + (srow1 * HP + sc1) * 2, gk + srow1 * 64 + sc1);
            cpa16(sV_u[nxt] + (srow0 * HP + sc0) * 2, gv + srow0 * 64 + sc0);
            cpa16(sV_u[nxt] + (srow1 * HP + sc1) * 2, gv + srow1 * 64 + sc1);
            CP_COMMIT();
        }

        int kb = kt * 64;
        #pragma unroll
        for (int g = 0; g < 4; g++) {
            // --- QK for nt = 2g, 2g+1 (keys 16g..16g+15) ---
            float e[2][4];
            #pragma unroll
            for (int u = 0; u < 2; u++) {
                int nt = 2 * g + u;
                #pragma unroll
                for (int j = 0; j < 4; j++) e[u][j] = 0.f;
                unsigned kb0 = sK_u[cur] + nt * 8 * HP * 2 + krow;
                unsigned bf[4], bf2[4];
                ldmx4(bf, kb0);
                ldmx4(bf2, kb0 + 64);
                mma_f16(e[u], qa[0], bf[0], bf[1]);
                mma_f16(e[u], qa[1], bf[2], bf[3]);
                mma_f16(e[u], qa[2], bf2[0], bf2[1]);
                mma_f16(e[u], qa[3], bf2[2], bf2[3]);
            }
            // --- softmax (no-shift): p = exp2(e * mask * SC2) ---
            unsigned pa[4];
            #pragma unroll
            for (int u = 0; u < 2; u++) {
                int nt = 2 * g + u;
                float2 mm0 = *(const float2*)&mrow0[kb + nt * 8 + 2 * c4];
                float2 mm1 = *(const float2*)&mrow1[kb + nt * 8 + 2 * c4];
                e[u][0] = exp2f(e[u][0] * (mm0.x * SC2));
                e[u][1] = exp2f(e[u][1] * (mm0.y * SC2));
                e[u][2] = exp2f(e[u][2] * (mm1.x * SC2));
                e[u][3] = exp2f(e[u][3] * (mm1.y * SC2));
                l0 += e[u][0] + e[u][1];
                l1 += e[u][2] + e[u][3];
                pa[2 * u] = h2u(e[u][0], e[u][1]);
                pa[2 * u + 1] = h2u(e[u][2], e[u][3]);
            }
            // pa order must be {rowlo(nt=2g), rowhi(nt=2g), rowlo(2g+1), rowhi(2g+1)}
            unsigned pfrag[4];
            pfrag[0] = pa[0];
            pfrag[1] = pa[1];
            pfrag[2] = pa[2];
            pfrag[3] = pa[3];
            // --- PV for kk = g ---
            #pragma unroll
            for (int ntp = 0; ntp < 4; ntp++) {
                unsigned vf[4];
                ldmx4t(vf, sV_u[cur] + (g * 16 * HP + ntp * 16) * 2 + vrow);
                mma_f16(o[2 * ntp], pfrag, vf[0], vf[1]);
                mma_f16(o[2 * ntp + 1], pfrag, vf[2], vf[3]);
            }
        }
    }

    // single end-of-loop reduction of l across the quad
    l0 += __shfl_xor_sync(0xffffffffu, l0, 1);
    l0 += __shfl_xor_sync(0xffffffffu, l0, 2);
    l1 += __shfl_xor_sync(0xffffffffu, l1, 1);
    l1 += __shfl_xor_sync(0xffffffffu, l1, 2);
    float inv0 = 1.f / l0, inv1 = 1.f / l1;
    size_t ob0 = ((size_t)(b * S + qw + r4)) * D + h * 64;
    size_t ob1 = ((size_t)(b * S + qw + r4 + 8)) * D + h * 64;
    #pragma unroll
    for (int nt = 0; nt < 8; nt++) {
        *(__half2*)&g_att[ob0 + nt * 8 + 2 * c4] = __floats2half2_rn(o[nt][0] * inv0, o[nt][1] * inv0);
        *(__half2*)&g_att[ob1 + nt * 8 + 2 * c4] = __floats2half2_rn(o[nt][2] * inv1, o[nt][3] * inv1);
    }
}

// ---------------- kernel 6: out = att @ Wo^T + bo (double-buffered fp16 mma) ----------------
__global__ void __launch_bounds__(256, 2) k_proj(const float* __restrict__ Wo,
                                                 const float* __restrict__ bo,
                                                 float* __restrict__ out) {
    extern __shared__ __half smh[];
    __half* sA[2] = {smh, smh + 128 * HP};
    __half* sB[2] = {smh + 2 * 128 * HP, smh + 2 * 128 * HP + 64 * HP};
    int tid = threadIdx.x;
    int w = tid >> 5, lane = tid & 31;
    int r4 = lane >> 2, c4 = lane & 3;
    int m0 = blockIdx.x * 128;
    int n0 = blockIdx.y * 64;

    unsigned s_u = (unsigned)__cvta_generic_to_shared(smh);
    unsigned sA_u[2] = {s_u, s_u + 128u * HP * 2};

    float acc[8][4];
    #pragma unroll
    for (int nt = 0; nt < 8; nt++)
        #pragma unroll
        for (int j = 0; j < 4; j++) acc[nt][j] = 0.f;

    auto stageA = [&](int buf, int k0) {
        #pragma unroll
        for (int t = 0; t < 4; t++) {
            int idx = tid + t * 256;
            int r = idx >> 3, c = (idx & 7) * 8;
            cpa16(sA_u[buf] + (r * HP + c) * 2, &g_att[(size_t)(m0 + r) * D + k0 + c]);
        }
    };
    auto stageB = [&](int buf, int k0) {
        #pragma unroll
        for (int t = 0; t < 4; t++) {
            int idx = tid + t * 256;
            int r = idx >> 4, c = (idx & 15) * 4;
            float4 v = *(const float4*)&Wo[(size_t)(n0 + r) * D + k0 + c];
            *(__half2*)&sB[buf][r * HP + c] = __floats2half2_rn(v.x, v.y);
            *(__half2*)&sB[buf][r * HP + c + 2] = __floats2half2_rn(v.z, v.w);
        }
    };

    stageA(0, 0);
    CP_COMMIT();
    stageB(0, 0);

    for (int kt = 0; kt < D / 64; kt++) {
        int cur = kt & 1;
        CP_WAIT0();
        __syncthreads();
        if (kt < D / 64 - 1) {
            stageA(cur ^ 1, (kt + 1) * 64);
            CP_COMMIT();
            stageB(cur ^ 1, (kt + 1) * 64);
        }

        const __half* Aw = sA[cur] + (w * 16) * HP;
        unsigned af[4][4];
        #pragma unroll
        for (int kk = 0; kk < 4; kk++) {
            af[kk][0] = *(const unsigned*)&Aw[r4 * HP + kk * 16 + 2 * c4];
            af[kk][1] = *(const unsigned*)&Aw[(r4 + 8) * HP + kk * 16 + 2 * c4];
            af[kk][2] = *(const unsigned*)&Aw[r4 * HP + kk * 16 + 2 * c4 + 8];
            af[kk][3] = *(const unsigned*)&Aw[(r4 + 8) * HP + kk * 16 + 2 * c4 + 8];
        }
        #pragma unroll
        for (int nt = 0; nt < 8; nt++) {
            #pragma unroll
            for (int kk = 0; kk < 4; kk++) {
                const __half* bp = &sB[cur][(nt * 8 + r4) * HP + kk * 16 + 2 * c4];
                unsigned b0 = *(const unsigned*)bp;
                unsigned b1 = *(const unsigned*)(bp + 8);
                mma_f16(acc[nt], af[kk], b0, b1);
            }
        }
    }

    int row0 = m0 + w * 16 + r4;
    #pragma unroll
    for (int nt = 0; nt < 8; nt++) {
        int n = n0 + nt * 8 + 2 * c4;
        float2 bb = *(const float2*)&bo[n];
        float2 v0, v1;
        v0.x = acc[nt][0] + bb.x; v0.y = acc[nt][1] + bb.y;
        v1.x = acc[nt][2] + bb.x; v1.y = acc[nt][3] + bb.y;
        *(float2*)&out[(size_t)row0 * D + n] = v0;
        *(float2*)&out[(size_t)(row0 + 8) * D + n] = v1;
    }
}

// ---------------- launch ----------------
extern "C" void kernel_launch(void* const* d_in, const int* in_sizes, int n_in,
                              void* d_out, int out_size) {
    const int*   x   = (const int*)d_in[0];
    const float* emb = (const float*)d_in[1];
    const float* Wq  = (const float*)d_in[2];
    const float* Wk  = (const float*)d_in[3];
    const float* Wv  = (const float*)d_in[4];
    const float* Wo  = (const float*)d_in[5];
    const float* bo  = (const float*)d_in[6];
    const float* Wc  = (const float*)d_in[7];
    const float* bc  = (const float*)d_in[8];
    float* out = (float*)d_out;
    float* maskout = out + (size_t)B * S * D;

    k_pe<<<S, 256>>>();
    k_embed<<<BS, 128>>>(x, emb, Wc, bc);
    k_norm<<<B, S>>>();
    dim3 mg(S, B);
    k_mask<<<mg, 256>>>(maskout);

    size_t qkv_smem = (128 * HP + 3 * 64 * HP) * sizeof(__half);
    cudaFuncSetAttribute(k_qkv, cudaFuncAttributeMaxDynamicSharedMemorySize, (int)qkv_smem);
    dim3 qg(BS / 128, H);
    k_qkv<<<qg, 256, qkv_smem>>>(Wq, Wk, Wv);

    size_t attn_smem = 4 * 64 * HP * sizeof(__half);
    cudaFuncSetAttribute(k_attn, cudaFuncAttributeMaxDynamicSharedMemorySize, (int)attn_smem);
    k_attn<<<B * H * (S / 128), 256, attn_smem>>>(maskout);

    size_t proj_smem = (2 * 128 * HP + 2 * 64 * HP) * sizeof(__half);
    cudaFuncSetAttribute(k_proj, cudaFuncAttributeMaxDynamicSharedMemorySize, (int)proj_smem);
    dim3 pg(BS / 128, D / 64);
    k_proj<<<pg, 256, proj_smem>>>(Wo, bo, out);
}